// round 12
// baseline (speedup 1.0000x reference)
#include <cuda_runtime.h>
#include <cuda_fp16.h>
#include <cstdint>

#define BSZ 16
#define TT  1024
#define EMB 768
#define HID 1024
#define MROWS (BSZ*TT)

// ================= scratch =================
__device__ __align__(128) __half  g_ABh [(size_t)2*MROWS*EMB];
__device__ __align__(128) uint8_t g_AB8 [(size_t)2*MROWS*2*EMB];
__device__ __align__(128) __half  g_W1Th[(size_t)HID*EMB];
__device__ __align__(128) uint8_t g_W1T8[(size_t)HID*2*EMB];
__device__ __align__(128) __half  g_W2Th[(size_t)HID*HID];
__device__ __align__(128) uint8_t g_W2T8[(size_t)HID*2*HID];
__device__ __align__(128) __half  g_Hh  [(size_t)2*MROWS*HID];
__device__ __align__(128) uint8_t g_H8  [(size_t)2*MROWS*2*HID];
__device__ __align__(128) __half  g_Fh  [(size_t)2*MROWS*HID];
__device__ __align__(128) uint8_t g_F8  [(size_t)2*MROWS*2*HID];
__device__ __align__(128) float   g_E   [(size_t)BSZ*TT*TT];
__device__ __align__(128) __half  g_Pall[(size_t)2*BSZ*TT*TT];
__device__ float g_rmax[MROWS], g_rsum[MROWS], g_cmax[MROWS], g_csum[MROWS];

// ================= helpers =================
__device__ __forceinline__ uint32_t smem_u32(const void* p) {
    uint32_t a;
    asm("{ .reg .u64 t; cvta.to.shared.u64 t, %1; cvt.u32.u64 %0, t; }" : "=r"(a) : "l"(p));
    return a;
}
__device__ __forceinline__ void mma_f16(float* d, const uint32_t* a, const uint32_t* b) {
    asm volatile("mma.sync.aligned.m16n8k16.row.col.f32.f16.f16.f32 "
        "{%0,%1,%2,%3}, {%4,%5,%6,%7}, {%8,%9}, {%0,%1,%2,%3};"
        : "+f"(d[0]), "+f"(d[1]), "+f"(d[2]), "+f"(d[3])
        : "r"(a[0]), "r"(a[1]), "r"(a[2]), "r"(a[3]), "r"(b[0]), "r"(b[1]));
}
__device__ __forceinline__ void mma_45(float* d, const uint32_t* a, const uint32_t* b) {
    asm volatile("mma.sync.aligned.m16n8k32.row.col.f32.e4m3.e5m2.f32 "
        "{%0,%1,%2,%3}, {%4,%5,%6,%7}, {%8,%9}, {%0,%1,%2,%3};"
        : "+f"(d[0]), "+f"(d[1]), "+f"(d[2]), "+f"(d[3])
        : "r"(a[0]), "r"(a[1]), "r"(a[2]), "r"(a[3]), "r"(b[0]), "r"(b[1]));
}
__device__ __forceinline__ void mma_54(float* d, const uint32_t* a, const uint32_t* b) {
    asm volatile("mma.sync.aligned.m16n8k32.row.col.f32.e5m2.e4m3.f32 "
        "{%0,%1,%2,%3}, {%4,%5,%6,%7}, {%8,%9}, {%0,%1,%2,%3};"
        : "+f"(d[0]), "+f"(d[1]), "+f"(d[2]), "+f"(d[3])
        : "r"(a[0]), "r"(a[1]), "r"(a[2]), "r"(a[3]), "r"(b[0]), "r"(b[1]));
}
__device__ __forceinline__ void ldsm(uint32_t* r, uint32_t a) {
    asm volatile("ldmatrix.sync.aligned.m8n8.x4.shared.b16 {%0,%1,%2,%3}, [%4];"
        : "=r"(r[0]), "=r"(r[1]), "=r"(r[2]), "=r"(r[3]) : "r"(a));
}
__device__ __forceinline__ void ldsmT(uint32_t* r, uint32_t a) {
    asm volatile("ldmatrix.sync.aligned.m8n8.x4.trans.shared.b16 {%0,%1,%2,%3}, [%4];"
        : "=r"(r[0]), "=r"(r[1]), "=r"(r[2]), "=r"(r[3]) : "r"(a));
}
__device__ __forceinline__ void cp16(uint32_t d, const void* s) {
    asm volatile("cp.async.cg.shared.global [%0], [%1], 16;" :: "r"(d), "l"(s) : "memory");
}
__device__ __forceinline__ uint16_t pk_e4m3(float v0, float v1) {
    uint16_t u; asm("cvt.rn.satfinite.e4m3x2.f32 %0, %1, %2;" : "=h"(u) : "f"(v1), "f"(v0)); return u;
}
__device__ __forceinline__ uint16_t pk_e5m2(float v0, float v1) {
    uint16_t u; asm("cvt.rn.satfinite.e5m2x2.f32 %0, %1, %2;" : "=h"(u) : "f"(v1), "f"(v0)); return u;
}

// ================= main GEMM: fp16 hi*hi + fp8 cross terms =================
// C = [act]( Ah*Bh^T + Ah8*Bl8^T + Al8*Bh8^T + bias )
#define BM 128
#define BN 128
#define BKH 32
#define NTHR 256
#define SROWH 80u
#define SROW8 48u
#define BHI_OFF 10240u
#define AH8_OFF 20480u
#define AL8_OFF 26624u
#define BH8_OFF 32768u
#define BL8_OFF 38912u
#define STGF 45056u
#define SMEMF (2*45056)

__device__ __forceinline__ void cp_stage_f(uint32_t st,
    const __half* gah, const uint8_t* ga8,
    const __half* gbh, const uint8_t* gb8, int K, int tid)
{
    const int K2 = 2 * K;
#pragma unroll
    for (int i = 0; i < 2; ++i) {
        int u = tid + i * NTHR, r = u >> 2, c = u & 3;
        cp16(st + (uint32_t)r * SROWH + c * 16, gah + (size_t)r * K + c * 8);
        cp16(st + BHI_OFF + (uint32_t)r * SROWH + c * 16, gbh + (size_t)r * K + c * 8);
    }
    {
        int r = tid >> 1, c = tid & 1;
        uint32_t o = (uint32_t)r * SROW8 + c * 16;
        size_t  g = (size_t)r * K2 + c * 16;
        cp16(st + AH8_OFF + o, ga8 + g);
        cp16(st + AL8_OFF + o, ga8 + K + g);
        cp16(st + BH8_OFF + o, gb8 + g);
        cp16(st + BL8_OFF + o, gb8 + K + g);
    }
}

template<bool BIASRELU, bool SPLITOUT>
__global__ void __launch_bounds__(NTHR, 2)
gemm_f8(const __half* __restrict__ Ah, const uint8_t* __restrict__ A8,
        const __half* __restrict__ Bh, const uint8_t* __restrict__ B8,
        unsigned long long sH, unsigned long long s8,
        const float* __restrict__ bias,
        __half* __restrict__ Ch, uint8_t* __restrict__ C8, float* __restrict__ Cf,
        int ldc, unsigned long long sC, int N, int K)
{
    extern __shared__ __align__(128) char smc[];
    uint32_t sb = smem_u32(smc);
    const int tid = threadIdx.x, lane = tid & 31, wid = tid >> 5;
    const int wm = wid >> 2, wn = wid & 3, gr = lane >> 2, tc = lane & 3;
    const int m0 = blockIdx.y * BM, n0 = blockIdx.x * BN, z = blockIdx.z;

    const __half*  Abh = Ah + (size_t)z * sH + (size_t)m0 * K;
    const uint8_t* Ab8 = A8 + (size_t)z * s8 + (size_t)m0 * 2 * K;
    const __half*  Bbh = Bh + (size_t)z * sH + (size_t)n0 * K;
    const uint8_t* Bb8 = B8 + (size_t)z * s8 + (size_t)n0 * 2 * K;
    const int NT = K / BKH;

    const int lg = lane >> 3, r8 = lane & 7;
    uint32_t aOH[4], aO8[4], bOH[2], bO8[2];
#pragma unroll
    for (int mi = 0; mi < 4; ++mi) {
        int row = wm * 64 + mi * 16 + (lg & 1) * 8 + r8;
        aOH[mi] = (uint32_t)row * SROWH + (lg >> 1) * 16;
        aO8[mi] = (uint32_t)row * SROW8 + (lg >> 1) * 16;
    }
#pragma unroll
    for (int pn = 0; pn < 2; ++pn) {
        int row = wn * 32 + pn * 16 + (lg >> 1) * 8 + r8;
        bOH[pn] = (uint32_t)row * SROWH + (lg & 1) * 16;
        bO8[pn] = (uint32_t)row * SROW8 + (lg & 1) * 16;
    }

    float acc[4][4][4];
#pragma unroll
    for (int i = 0; i < 4; ++i)
#pragma unroll
        for (int j = 0; j < 4; ++j)
#pragma unroll
            for (int k = 0; k < 4; ++k) acc[i][j][k] = 0.f;

    cp_stage_f(sb, Abh, Ab8, Bbh, Bb8, K, tid);
    asm volatile("cp.async.commit_group;" ::: "memory");

#pragma unroll 1
    for (int kt = 0; kt < NT; ++kt) {
        asm volatile("cp.async.wait_group 0;" ::: "memory");
        __syncthreads();
        if (kt + 1 < NT) {
            uint32_t st = sb + (uint32_t)((kt + 1) & 1) * STGF;
            cp_stage_f(st, Abh + (kt + 1) * BKH, Ab8 + (kt + 1) * BKH,
                       Bbh + (kt + 1) * BKH, Bb8 + (kt + 1) * BKH, K, tid);
            asm volatile("cp.async.commit_group;" ::: "memory");
        }
        uint32_t st = sb + (uint32_t)(kt & 1) * STGF;

        // fp16 hi*hi
#pragma unroll
        for (int ks = 0; ks < 2; ++ks) {
            const uint32_t kb = (uint32_t)(ks * 32);
            uint32_t bf[4][2];
#pragma unroll
            for (int pn = 0; pn < 2; ++pn) {
                uint32_t t[4]; ldsm(t, st + BHI_OFF + bOH[pn] + kb);
                bf[2*pn][0]=t[0]; bf[2*pn][1]=t[1]; bf[2*pn+1][0]=t[2]; bf[2*pn+1][1]=t[3];
            }
#pragma unroll
            for (int mi = 0; mi < 4; ++mi) {
                uint32_t af[4]; ldsm(af, st + aOH[mi] + kb);
#pragma unroll
                for (int ni = 0; ni < 4; ++ni) mma_f16(acc[mi][ni], af, bf[ni]);
            }
        }
        // fp8 cross (k32, one shot)
        {
            uint32_t bh[4][2], bl[4][2];
#pragma unroll
            for (int pn = 0; pn < 2; ++pn) {
                uint32_t t[4];
                ldsm(t, st + BH8_OFF + bO8[pn]);
                bh[2*pn][0]=t[0]; bh[2*pn][1]=t[1]; bh[2*pn+1][0]=t[2]; bh[2*pn+1][1]=t[3];
                ldsm(t, st + BL8_OFF + bO8[pn]);
                bl[2*pn][0]=t[0]; bl[2*pn][1]=t[1]; bl[2*pn+1][0]=t[2]; bl[2*pn+1][1]=t[3];
            }
#pragma unroll
            for (int mi = 0; mi < 4; ++mi) {
                uint32_t ah[4], al[4];
                ldsm(ah, st + AH8_OFF + aO8[mi]);
                ldsm(al, st + AL8_OFF + aO8[mi]);
#pragma unroll
                for (int ni = 0; ni < 4; ++ni) mma_45(acc[mi][ni], ah, bl[ni]);
#pragma unroll
                for (int ni = 0; ni < 4; ++ni) mma_54(acc[mi][ni], al, bh[ni]);
            }
        }
    }

#pragma unroll
    for (int ni = 0; ni < 4; ++ni) {
        int col = n0 + wn * 32 + ni * 8 + 2 * tc;
        float b0 = 0.f, b1 = 0.f;
        if (BIASRELU) { b0 = __ldg(bias + col); b1 = __ldg(bias + col + 1); }
#pragma unroll
        for (int mi = 0; mi < 4; ++mi) {
            int row0 = m0 + wm * 64 + mi * 16 + gr;
            float v00 = acc[mi][ni][0], v01 = acc[mi][ni][1];
            float v10 = acc[mi][ni][2], v11 = acc[mi][ni][3];
            if (BIASRELU) {
                v00 = fmaxf(v00 + b0, 0.f); v01 = fmaxf(v01 + b1, 0.f);
                v10 = fmaxf(v10 + b0, 0.f); v11 = fmaxf(v11 + b1, 0.f);
            }
            if (SPLITOUT) {
                __half2 h0 = __floats2half2_rn(v00, v01);
                __half2 h1 = __floats2half2_rn(v10, v11);
                __half* CH = Ch + (size_t)z * sC;
                *(__half2*)(CH + (size_t)row0 * ldc + col) = h0;
                *(__half2*)(CH + (size_t)(row0 + 8) * ldc + col) = h1;
                uint8_t* CP = C8 + (size_t)z * sC * 2;
                size_t r0c = (size_t)row0 * 2 * ldc + col;
                size_t r1c = (size_t)(row0 + 8) * 2 * ldc + col;
                *(uint16_t*)(CP + r0c) = pk_e4m3(v00, v01);
                *(uint16_t*)(CP + r1c) = pk_e4m3(v10, v11);
                *(uint16_t*)(CP + r0c + ldc) =
                    pk_e5m2(v00 - __half2float(__low2half(h0)), v01 - __half2float(__high2half(h0)));
                *(uint16_t*)(CP + r1c + ldc) =
                    pk_e5m2(v10 - __half2float(__low2half(h1)), v11 - __half2float(__high2half(h1)));
            } else {
                float* C = Cf + (size_t)z * sC;
                *(float2*)(C + (size_t)row0 * ldc + col) = make_float2(v00, v01);
                *(float2*)(C + (size_t)(row0 + 8) * ldc + col) = make_float2(v10, v11);
            }
        }
    }
}

// ================= beta/alpha GEMM (fp16 NN trans-B) =================
#define SROWT 272u
#define BT_OFF 10240u
#define STGP 18944u
#define SMEMP (2*18944)

__global__ void __launch_bounds__(NTHR, 2)
gemm_pa(const __half* __restrict__ Aop, const __half* __restrict__ Bop, int ldb,
        unsigned long long sB, float* __restrict__ Cv, int ldc,
        unsigned long long sC, int N, int K)
{
    extern __shared__ __align__(128) char smc[];
    uint32_t sb = smem_u32(smc);
    const int tid = threadIdx.x, lane = tid & 31, wid = tid >> 5;
    const int wm = wid >> 2, wn = wid & 3, gr = lane >> 2, tc = lane & 3;
    const int m0 = blockIdx.y * BM, n0 = blockIdx.x * BN, z = blockIdx.z;

    const __half* Ab = Aop + (size_t)z * TT * TT + (size_t)m0 * K;
    const __half* Bb = Bop + (size_t)z * sB + n0;
    const int NT = K / BKH;

    const int lg = lane >> 3, r8 = lane & 7;
    uint32_t aO[4], bO[2];
#pragma unroll
    for (int mi = 0; mi < 4; ++mi)
        aO[mi] = (uint32_t)(wm * 64 + mi * 16 + (lg & 1) * 8 + r8) * SROWH + (lg >> 1) * 16;
#pragma unroll
    for (int pn = 0; pn < 2; ++pn)
        bO[pn] = (uint32_t)((lg & 1) * 8 + r8) * SROWT + (wn * 32 + pn * 16 + (lg >> 1) * 8) * 2;

    float acc[4][4][4];
#pragma unroll
    for (int i = 0; i < 4; ++i)
#pragma unroll
        for (int j = 0; j < 4; ++j)
#pragma unroll
            for (int k = 0; k < 4; ++k) acc[i][j][k] = 0.f;

    auto stage = [&](int kt) {
        uint32_t st = sb + (uint32_t)(kt & 1) * STGP;
#pragma unroll
        for (int i = 0; i < 2; ++i) {
            int u = tid + i * NTHR, r = u >> 2, c = u & 3;
            cp16(st + (uint32_t)r * SROWH + c * 16, Ab + kt * BKH + (size_t)r * K + c * 8);
        }
#pragma unroll
        for (int i = 0; i < 2; ++i) {
            int u = tid + i * NTHR, r = u >> 4, c = u & 15;
            cp16(st + BT_OFF + (uint32_t)r * SROWT + c * 16,
                 Bb + (size_t)(kt * BKH + r) * ldb + c * 8);
        }
        asm volatile("cp.async.commit_group;" ::: "memory");
    };
    stage(0);

#pragma unroll 1
    for (int kt = 0; kt < NT; ++kt) {
        asm volatile("cp.async.wait_group 0;" ::: "memory");
        __syncthreads();
        if (kt + 1 < NT) stage(kt + 1);
        uint32_t st = sb + (uint32_t)(kt & 1) * STGP;
#pragma unroll
        for (int ks = 0; ks < 2; ++ks) {
            uint32_t bf[4][2];
#pragma unroll
            for (int pn = 0; pn < 2; ++pn) {
                uint32_t t[4];
                ldsmT(t, st + BT_OFF + bO[pn] + (uint32_t)(ks * 16 * SROWT));
                bf[2*pn][0]=t[0]; bf[2*pn][1]=t[1]; bf[2*pn+1][0]=t[2]; bf[2*pn+1][1]=t[3];
            }
#pragma unroll
            for (int mi = 0; mi < 4; ++mi) {
                uint32_t af[4]; ldsm(af, st + aO[mi] + (uint32_t)(ks * 32));
#pragma unroll
                for (int ni = 0; ni < 4; ++ni) mma_f16(acc[mi][ni], af, bf[ni]);
            }
        }
    }

    const int ob = (z < BSZ) ? (BSZ + z) : (z - BSZ);
    float* C = Cv + (size_t)ob * sC;
#pragma unroll
    for (int ni = 0; ni < 4; ++ni) {
        int col = n0 + wn * 32 + ni * 8 + 2 * tc;
#pragma unroll
        for (int mi = 0; mi < 4; ++mi) {
            int row0 = m0 + wm * 64 + mi * 16 + gr;
            *(float2*)(C + (size_t)row0 * ldc + col) = make_float2(acc[mi][ni][0], acc[mi][ni][1]);
            *(float2*)(C + (size_t)(row0 + 8) * ldc + col) = make_float2(acc[mi][ni][2], acc[mi][ni][3]);
        }
    }
}

// ================= prep =================
#define NSPA ((MROWS*EMB)/1024)
#define NW1  ((EMB/32)*(HID/32))
#define NW2  ((HID/32)*(HID/32))
#define PREP_BLOCKS (2*NSPA + NW1 + NW2)

__global__ void __launch_bounds__(256)
prep_kernel(const float* __restrict__ A, const float* __restrict__ Bn,
            const float* __restrict__ W1, const float* __restrict__ W2,
            __half* __restrict__ ABh, uint8_t* __restrict__ AB8,
            __half* __restrict__ W1Th, uint8_t* __restrict__ W1T8,
            __half* __restrict__ W2Th, uint8_t* __restrict__ W2T8)
{
    __shared__ float tile[32][33];
    int id = blockIdx.x, tid = threadIdx.x;

    if (id < 2 * NSPA) {
        bool isA = id < NSPA;
        const float4* src = (const float4*)(isA ? A : Bn);
        size_t i = (size_t)(id - (isA ? 0 : NSPA)) * 256 + tid;
        float4 v = src[i];
        size_t row = i / (EMB/4) + (isA ? 0 : (size_t)MROWS);
        size_t c = (i % (EMB/4)) * 4;
        __half2 h01 = __floats2half2_rn(v.x, v.y);
        __half2 h23 = __floats2half2_rn(v.z, v.w);
        __half* dh = ABh + row * EMB + c;
        *(__half2*)dh = h01; *(__half2*)(dh + 2) = h23;
        uint8_t* d8 = AB8 + row * 2 * EMB + c;
        *(uint16_t*)d8       = pk_e4m3(v.x, v.y);
        *(uint16_t*)(d8 + 2) = pk_e4m3(v.z, v.w);
        float l0 = v.x - __half2float(__low2half(h01));
        float l1 = v.y - __half2float(__high2half(h01));
        float l2 = v.z - __half2float(__low2half(h23));
        float l3 = v.w - __half2float(__high2half(h23));
        *(uint16_t*)(d8 + EMB)     = pk_e5m2(l0, l1);
        *(uint16_t*)(d8 + EMB + 2) = pk_e5m2(l2, l3);
        return;
    }
    id -= 2 * NSPA;
    int tx = tid & 31, ty = tid >> 5;
    bool isW1 = id < NW1;
    int id2 = isW1 ? id : id - NW1;
    int R = isW1 ? EMB : HID;
    const float* W = isW1 ? W1 : W2;
    __half* WTh = isW1 ? W1Th : W2Th;
    uint8_t* WT8 = isW1 ? W1T8 : W2T8;
    int rt = R / 32;
    int r0 = (id2 % rt) * 32, c0 = (id2 / rt) * 32;
#pragma unroll
    for (int k = 0; k < 4; ++k)
        tile[k*8+ty][tx] = W[(size_t)(r0 + k*8 + ty) * HID + c0 + tx];
    __syncthreads();
#pragma unroll
    for (int k = 0; k < 4; ++k) {
        int c = c0 + k*8 + ty;
        float v = tile[tx][k*8+ty];
        __half h = __float2half_rn(v);
        WTh[(size_t)c * R + r0 + tx] = h;
        float l = v - __half2float(h);
        uint8_t* p = WT8 + (size_t)c * 2 * R;
        uint16_t u4 = pk_e4m3(v, 0.f), u5 = pk_e5m2(l, 0.f);
        p[r0 + tx]     = (uint8_t)u4;
        p[R + r0 + tx] = (uint8_t)u5;
    }
}

// ================= softmax =================
#define ROWSTAT_BLOCKS (MROWS/8)
__global__ void __launch_bounds__(256)
stats_kernel(const float* __restrict__ E, float* __restrict__ rmax, float* __restrict__ rsum,
             float* __restrict__ cmax, float* __restrict__ csum)
{
    if (blockIdx.x < ROWSTAT_BLOCKS) {
        int r = blockIdx.x * 8 + (threadIdx.x >> 5);
        int lane = threadIdx.x & 31;
        const float* row = E + (size_t)r * TT;
        float v[32], m = -1e30f;
#pragma unroll
        for (int i = 0; i < 8; ++i) {
            float4 t = *(const float4*)(row + i*128 + lane*4);
            v[i*4]=t.x; v[i*4+1]=t.y; v[i*4+2]=t.z; v[i*4+3]=t.w;
            m = fmaxf(m, fmaxf(fmaxf(t.x,t.y), fmaxf(t.z,t.w)));
        }
#pragma unroll
        for (int o = 16; o > 0; o >>= 1) m = fmaxf(m, __shfl_xor_sync(~0u, m, o));
        float s = 0.f;
#pragma unroll
        for (int i = 0; i < 32; ++i) s += __expf(v[i] - m);
#pragma unroll
        for (int o = 16; o > 0; o >>= 1) s += __shfl_xor_sync(~0u, s, o);
        if (lane == 0) { rmax[r] = m; rsum[r] = s; }
    } else {
        int id = blockIdx.x - ROWSTAT_BLOCKS;
        int b = id >> 2, c = ((id & 3) << 8) + threadIdx.x;
        const float* base = E + (size_t)b * TT * TT + c;
        float m = -1e30f;
#pragma unroll 8
        for (int a = 0; a < TT; ++a) m = fmaxf(m, base[(size_t)a * TT]);
        float s = 0.f;
#pragma unroll 8
        for (int a = 0; a < TT; ++a) s += __expf(base[(size_t)a * TT] - m);
        cmax[b*TT+c] = m; csum[b*TT+c] = s;
    }
}

__global__ void __launch_bounds__(256)
normexp_kernel(const float* __restrict__ E, __half* __restrict__ Pall,
               const float* __restrict__ rmax, const float* __restrict__ rsum,
               const float* __restrict__ cmax, const float* __restrict__ csum)
{
    __shared__ float tile[32][33];
    int b = blockIdx.z, a0 = blockIdx.y * 32, c0 = blockIdx.x * 32;
    int tx = threadIdx.x, ty = threadIdx.y;
    const float* Eb = E + (size_t)b * TT * TT;
    __half* P2b = Pall + (size_t)b * TT * TT;
    __half* Pb  = Pall + (size_t)(BSZ + b) * TT * TT;
#pragma unroll
    for (int k = 0; k < 4; ++k) {
        int a = a0 + k*8 + ty;
        float v = Eb[(size_t)a * TT + c0 + tx];
        tile[k*8+ty][tx] = v;
        int grr = b * TT + a;
        Pb[(size_t)a * TT + c0 + tx] = __float2half_rn(__expf(v - rmax[grr]) * __frcp_rn(rsum[grr]));
    }
    __syncthreads();
#pragma unroll
    for (int k = 0; k < 4; ++k) {
        int c = c0 + k*8 + ty;
        float v = tile[tx][k*8+ty];
        int gc = b * TT + c;
        P2b[(size_t)c * TT + a0 + tx] = __float2half_rn(__expf(v - cmax[gc]) * __frcp_rn(csum[gc]));
    }
}

// ================= launch =================
extern "C" void kernel_launch(void* const* d_in, const int* in_sizes, int n_in,
                              void* d_out, int out_size)
{
    const float* Ain = (const float*)d_in[0];
    const float* Bin = (const float*)d_in[1];
    const float* W1  = (const float*)d_in[2];
    const float* b1  = (const float*)d_in[3];
    const float* W2  = (const float*)d_in[4];
    const float* b2  = (const float*)d_in[5];
    float* outp = (float*)d_out;

    __half *ABh, *W1Th, *W2Th, *Hh, *Fh, *Pall;
    uint8_t *AB8, *W1T8, *W2T8, *H8, *F8;
    float *E, *rm, *rs, *cm, *cs;
    cudaGetSymbolAddress((void**)&ABh, g_ABh);   cudaGetSymbolAddress((void**)&AB8, g_AB8);
    cudaGetSymbolAddress((void**)&W1Th, g_W1Th); cudaGetSymbolAddress((void**)&W1T8, g_W1T8);
    cudaGetSymbolAddress((void**)&W2Th, g_W2Th); cudaGetSymbolAddress((void**)&W2T8, g_W2T8);
    cudaGetSymbolAddress((void**)&Hh, g_Hh);     cudaGetSymbolAddress((void**)&H8, g_H8);
    cudaGetSymbolAddress((void**)&Fh, g_Fh);     cudaGetSymbolAddress((void**)&F8, g_F8);
    cudaGetSymbolAddress((void**)&E, g_E);       cudaGetSymbolAddress((void**)&Pall, g_Pall);
    cudaGetSymbolAddress((void**)&rm, g_rmax);   cudaGetSymbolAddress((void**)&rs, g_rsum);
    cudaGetSymbolAddress((void**)&cm, g_cmax);   cudaGetSymbolAddress((void**)&cs, g_csum);

    cudaFuncSetAttribute(gemm_f8<true,  true >, cudaFuncAttributeMaxDynamicSharedMemorySize, SMEMF);
    cudaFuncSetAttribute(gemm_f8<false, false>, cudaFuncAttributeMaxDynamicSharedMemorySize, SMEMF);

    prep_kernel<<<PREP_BLOCKS, 256>>>(Ain, Bin, W1, W2, ABh, AB8, W1Th, W1T8, W2Th, W2T8);

    // layer 1: Hh/H8 = splitout(relu(X @ W1 + b1)), K=EMB
    gemm_f8<true, true><<<dim3(HID/BN, 2*MROWS/BM, 1), NTHR, SMEMF>>>(
        ABh, AB8, W1Th, W1T8, 0, 0, b1, Hh, H8, nullptr, HID, 0, HID, EMB);

    // layer 2: Fh/F8 = splitout(relu(H @ W2 + b2)), K=HID
    gemm_f8<true, true><<<dim3(HID/BN, 2*MROWS/BM, 1), NTHR, SMEMF>>>(
        Hh, H8, W2Th, W2T8, 0, 0, b2, Fh, F8, nullptr, HID, 0, HID, HID);

    // e = f_A @ f_B^T (f32 out), batched
    gemm_f8<false, false><<<dim3(TT/BN, TT/BM, BSZ), NTHR, SMEMF>>>(
        Fh, F8, Fh + (size_t)MROWS*HID, F8 + (size_t)MROWS*2*HID,
        (unsigned long long)TT*HID, (unsigned long long)TT*2*HID,
        nullptr, nullptr, nullptr, E, TT, (unsigned long long)TT*TT, TT, HID);

    stats_kernel<<<ROWSTAT_BLOCKS + BSZ*4, 256>>>(E, rm, rs, cm, cs);
    normexp_kernel<<<dim3(TT/32, TT/32, BSZ), dim3(32, 8)>>>(E, Pall, rm, rs, cm, cs);

    // alpha (z 0..15: P2 @ A) and beta (z 16..31: P @ B); B = fp16 hi of inputs
    gemm_pa<<<dim3(EMB/BN, TT/BM, 2*BSZ), NTHR, SMEMP>>>(
        Pall, ABh, EMB, (unsigned long long)TT*EMB,
        outp, EMB, (unsigned long long)TT*EMB, EMB, TT);
}

// round 13
// speedup vs baseline: 1.2674x; 1.2674x over previous
#include <cuda_runtime.h>
#include <cuda_fp16.h>
#include <cstdint>

#define BSZ 16
#define TT  1024
#define EMB 768
#define HID 1024
#define MROWS (BSZ*TT)

// ================= scratch =================
__device__ __align__(128) __half g_ABh [(size_t)2*MROWS*2*EMB];
__device__ __align__(128) __half g_W1Th[(size_t)HID*2*EMB];
__device__ __align__(128) __half g_W2Th[(size_t)HID*2*HID];
__device__ __align__(128) __half g_Hh  [(size_t)2*MROWS*2*HID];
__device__ __align__(128) __half g_Fh  [(size_t)2*MROWS*2*HID];
__device__ __align__(128) float  g_E   [(size_t)2*BSZ*TT*TT];   // two K-halves
__device__ __align__(128) __half g_Pall[(size_t)2*BSZ*TT*TT];   // [P2 | P]
__device__ float g_rmax[MROWS], g_rsum[MROWS], g_cmax[MROWS], g_csum[MROWS];
__device__ float g_cpm[8*MROWS], g_cps[8*MROWS];                // col partials

// ================= helpers =================
__device__ __forceinline__ uint32_t smem_u32(const void* p) {
    uint32_t a;
    asm("{ .reg .u64 t; cvta.to.shared.u64 t, %1; cvt.u32.u64 %0, t; }" : "=r"(a) : "l"(p));
    return a;
}
__device__ __forceinline__ void mma_f16(float* d, const uint32_t* a, const uint32_t* b) {
    asm volatile("mma.sync.aligned.m16n8k16.row.col.f32.f16.f16.f32 "
        "{%0,%1,%2,%3}, {%4,%5,%6,%7}, {%8,%9}, {%0,%1,%2,%3};"
        : "+f"(d[0]), "+f"(d[1]), "+f"(d[2]), "+f"(d[3])
        : "r"(a[0]), "r"(a[1]), "r"(a[2]), "r"(a[3]), "r"(b[0]), "r"(b[1]));
}
__device__ __forceinline__ void ldsm(uint32_t* r, uint32_t a) {
    asm volatile("ldmatrix.sync.aligned.m8n8.x4.shared.b16 {%0,%1,%2,%3}, [%4];"
        : "=r"(r[0]), "=r"(r[1]), "=r"(r[2]), "=r"(r[3]) : "r"(a));
}
__device__ __forceinline__ void ldsmT(uint32_t* r, uint32_t a) {
    asm volatile("ldmatrix.sync.aligned.m8n8.x4.trans.shared.b16 {%0,%1,%2,%3}, [%4];"
        : "=r"(r[0]), "=r"(r[1]), "=r"(r[2]), "=r"(r[3]) : "r"(a));
}
__device__ __forceinline__ void cp16(uint32_t d, const void* s) {
    asm volatile("cp.async.cg.shared.global [%0], [%1], 16;" :: "r"(d), "l"(s) : "memory");
}
__device__ __forceinline__ void split_h(float v, __half& hi, __half& lo) {
    hi = __float2half_rn(v);
    lo = __float2half_rn(v - __half2float(hi));
}

// ================= fp16 mma GEMM (fused 3-term split) =================
// SPLIT3: C = [act](Ah*Bh^T + Ah*Bl^T + Al*Bh^T + bias); lo at col offset loK.
// !SPLIT3: C = A(M,K) * B(K,N), B row-major via ldmatrix.trans (beta/alpha).
// KSPLIT: gridDim.z = 2*BSZ; z&15 = batch, z>>4 = K-half; out to E-half buffer.
#define BM 128
#define BN 128
#define BKH 32
#define NTHR 256
#define SROW 80
#define SROWT 272
#define STG3 40960u
#define STGP 18944u
#define ALO_OFF 10240u
#define BHI_OFF 20480u
#define BLO_OFF 30720u
#define BT_OFF  10240u
#define SMEM3 (2*40960)
#define SMEMP (2*18944)

template<bool SPLIT3>
__device__ __forceinline__ void cp_stage32(uint32_t st,
    const __half* __restrict__ ga, int lda,
    const __half* __restrict__ gb, int ldb, int loK, int tid)
{
    if (SPLIT3) {
#pragma unroll
        for (int i = 0; i < 8; ++i) {
            int u = tid + i * NTHR;
            int mat = u >> 9;                // 0:Ahi 1:Alo 2:Bhi 3:Blo
            int r = (u >> 2) & 127;
            int c = u & 3;
            const __half* src = ((mat < 2) ? ga : gb)
                              + ((mat & 1) ? loK : 0)
                              + (size_t)r * ((mat < 2) ? lda : ldb) + c * 8;
            cp16(st + (uint32_t)((mat * 128 + r) * SROW + c * 16), src);
        }
    } else {
#pragma unroll
        for (int i = 0; i < 2; ++i) {
            int u = tid + i * NTHR, r = u >> 2, c = u & 3;
            cp16(st + (uint32_t)(r * SROW + c * 16), ga + (size_t)r * lda + c * 8);
        }
#pragma unroll
        for (int i = 0; i < 2; ++i) {
            int u = tid + i * NTHR, r = u >> 4, c = u & 15;
            cp16(st + BT_OFF + (uint32_t)(r * SROWT + c * 16), gb + (size_t)r * ldb + c * 8);
        }
    }
}

template<bool SPLIT3, bool BIASRELU, bool HALFSPLITOUT, bool SWAPOUT, bool KSPLIT>
__global__ void __launch_bounds__(NTHR, 2)
gemm_h(const __half* __restrict__ Aop, int lda, unsigned long long sA,
       const __half* __restrict__ Bop, int ldb, unsigned long long sB,
       const float* __restrict__ bias,
       void* __restrict__ Cv, int ldc, unsigned long long sC,
       int N, int K, int loK)
{
    extern __shared__ __align__(128) __half smh[];
    uint32_t sbase = smem_u32(smh);
    constexpr uint32_t STG = SPLIT3 ? STG3 : STGP;
    const int tid = threadIdx.x, lane = tid & 31, wid = tid >> 5;
    const int wm = wid >> 2, wn = wid & 3, gr = lane >> 2, tc = lane & 3;
    const int m0 = blockIdx.y * BM, n0 = blockIdx.x * BN;
    const int z  = blockIdx.z;
    const int zb   = KSPLIT ? (z & (BSZ - 1)) : z;
    const int half = KSPLIT ? (z >> 4) : 0;
    const int koff = half * K;

    const __half* Abase = Aop + (size_t)zb * sA + (size_t)m0 * lda + koff;
    const __half* Bbase = SPLIT3
        ? (Bop + (size_t)zb * sB + (size_t)n0 * ldb + koff)
        : (Bop + (size_t)zb * sB + n0);
    const int NT = K / BKH;

    const int lg = lane >> 3, r8 = lane & 7;
    uint32_t aOff[4], bOff[2];
#pragma unroll
    for (int mi = 0; mi < 4; ++mi)
        aOff[mi] = (uint32_t)((wm * 64 + mi * 16 + (lg & 1) * 8 + r8) * SROW
                              + (lg >> 1) * 16);
#pragma unroll
    for (int pn = 0; pn < 2; ++pn) {
        if (SPLIT3)
            bOff[pn] = (uint32_t)((wn * 32 + pn * 16 + (lg >> 1) * 8 + r8) * SROW
                                  + (lg & 1) * 16);
        else
            bOff[pn] = (uint32_t)(((lg & 1) * 8 + r8) * SROWT
                                  + (wn * 32 + pn * 16 + (lg >> 1) * 8) * 2);
    }

    float acc[4][4][4];
#pragma unroll
    for (int i = 0; i < 4; ++i)
#pragma unroll
        for (int j = 0; j < 4; ++j)
#pragma unroll
            for (int k = 0; k < 4; ++k) acc[i][j][k] = 0.f;

    cp_stage32<SPLIT3>(sbase, Abase, lda, Bbase, ldb, loK, tid);
    asm volatile("cp.async.commit_group;" ::: "memory");

#pragma unroll 1
    for (int kt = 0; kt < NT; ++kt) {
        asm volatile("cp.async.wait_group 0;" ::: "memory");
        __syncthreads();
        if (kt + 1 < NT) {
            uint32_t st = sbase + (uint32_t)((kt + 1) & 1) * STG;
            const __half* ga = Abase + (kt + 1) * BKH;
            const __half* gb = SPLIT3 ? (Bbase + (kt + 1) * BKH)
                                      : (Bbase + (size_t)(kt + 1) * BKH * ldb);
            cp_stage32<SPLIT3>(st, ga, lda, gb, ldb, loK, tid);
            asm volatile("cp.async.commit_group;" ::: "memory");
        }
        uint32_t st = sbase + (uint32_t)(kt & 1) * STG;
#pragma unroll
        for (int ks = 0; ks < 2; ++ks) {
            if (SPLIT3) {
                const uint32_t kb = (uint32_t)(ks * 32);
                uint32_t bh[4][2], bl[4][2];
#pragma unroll
                for (int pn = 0; pn < 2; ++pn) {
                    uint32_t t[4];
                    ldsm(t, st + BHI_OFF + bOff[pn] + kb);
                    bh[2*pn][0]=t[0]; bh[2*pn][1]=t[1]; bh[2*pn+1][0]=t[2]; bh[2*pn+1][1]=t[3];
                    ldsm(t, st + BLO_OFF + bOff[pn] + kb);
                    bl[2*pn][0]=t[0]; bl[2*pn][1]=t[1]; bl[2*pn+1][0]=t[2]; bl[2*pn+1][1]=t[3];
                }
#pragma unroll
                for (int mi = 0; mi < 4; ++mi) {
                    uint32_t ah[4], al[4];
                    ldsm(ah, st + aOff[mi] + kb);
                    ldsm(al, st + ALO_OFF + aOff[mi] + kb);
#pragma unroll
                    for (int ni = 0; ni < 4; ++ni) mma_f16(acc[mi][ni], ah, bh[ni]);
#pragma unroll
                    for (int ni = 0; ni < 4; ++ni) mma_f16(acc[mi][ni], al, bh[ni]);
#pragma unroll
                    for (int ni = 0; ni < 4; ++ni) mma_f16(acc[mi][ni], ah, bl[ni]);
                }
            } else {
                const uint32_t kbA = (uint32_t)(ks * 32);
                const uint32_t kbB = (uint32_t)(ks * 16 * SROWT);
                uint32_t bf[4][2];
#pragma unroll
                for (int pn = 0; pn < 2; ++pn) {
                    uint32_t t[4];
                    ldsmT(t, st + BT_OFF + bOff[pn] + kbB);
                    bf[2*pn][0]=t[0]; bf[2*pn][1]=t[1]; bf[2*pn+1][0]=t[2]; bf[2*pn+1][1]=t[3];
                }
#pragma unroll
                for (int mi = 0; mi < 4; ++mi) {
                    uint32_t af[4];
                    ldsm(af, st + aOff[mi] + kbA);
#pragma unroll
                    for (int ni = 0; ni < 4; ++ni) mma_f16(acc[mi][ni], af, bf[ni]);
                }
            }
        }
    }

    int ob = SWAPOUT ? ((z < BSZ) ? (BSZ + z) : (z - BSZ)) : zb;
    const size_t outoff = (size_t)ob * sC
                        + (KSPLIT ? (size_t)half * BSZ * sC : 0);
#pragma unroll
    for (int ni = 0; ni < 4; ++ni) {
        int col = n0 + wn * 32 + ni * 8 + 2 * tc;
        float b0 = 0.f, b1 = 0.f;
        if (BIASRELU) { b0 = __ldg(bias + col); b1 = __ldg(bias + col + 1); }
#pragma unroll
        for (int mi = 0; mi < 4; ++mi) {
            int row0 = m0 + wm * 64 + mi * 16 + gr;
            float v00 = acc[mi][ni][0], v01 = acc[mi][ni][1];
            float v10 = acc[mi][ni][2], v11 = acc[mi][ni][3];
            if (BIASRELU) {
                v00 = fmaxf(v00 + b0, 0.f); v01 = fmaxf(v01 + b1, 0.f);
                v10 = fmaxf(v10 + b0, 0.f); v11 = fmaxf(v11 + b1, 0.f);
            }
            if (HALFSPLITOUT) {
                __half* C = (__half*)Cv + outoff;
                __half h00,l00,h01,l01,h10,l10,h11,l11;
                split_h(v00,h00,l00); split_h(v01,h01,l01);
                split_h(v10,h10,l10); split_h(v11,h11,l11);
                __half* p0 = C + (size_t)row0 * ldc + col;
                __half* p1 = C + (size_t)(row0 + 8) * ldc + col;
                *(__half2*)p0       = __halves2half2(h00, h01);
                *(__half2*)(p0 + N) = __halves2half2(l00, l01);
                *(__half2*)p1       = __halves2half2(h10, h11);
                *(__half2*)(p1 + N) = __halves2half2(l10, l11);
            } else {
                float* C = (float*)Cv + outoff;
                *(float2*)(C + (size_t)row0 * ldc + col)       = make_float2(v00, v01);
                *(float2*)(C + (size_t)(row0 + 8) * ldc + col) = make_float2(v10, v11);
            }
        }
    }
}

// ================= prep =================
#define NSPA ((MROWS*EMB)/1024)
#define NW1  ((EMB/32)*(HID/32))
#define NW2  ((HID/32)*(HID/32))
#define PREP_BLOCKS (2*NSPA + NW1 + NW2)

__global__ void __launch_bounds__(256)
prep_kernel(const float* __restrict__ A, const float* __restrict__ Bn,
            const float* __restrict__ W1, const float* __restrict__ W2,
            __half* __restrict__ ABh, __half* __restrict__ W1Th,
            __half* __restrict__ W2Th)
{
    __shared__ float tile[32][33];
    int id = blockIdx.x, tid = threadIdx.x;
    if (id < 2 * NSPA) {
        bool isA = id < NSPA;
        const float4* src = (const float4*)(isA ? A : Bn);
        size_t i = (size_t)(id - (isA ? 0 : NSPA)) * 256 + tid;
        float4 v = src[i];
        size_t row = i / (EMB/4) + (isA ? 0 : (size_t)MROWS);
        size_t c = (i % (EMB/4)) * 4;
        __half h0,l0,h1,l1,h2,l2,h3,l3;
        split_h(v.x,h0,l0); split_h(v.y,h1,l1); split_h(v.z,h2,l2); split_h(v.w,h3,l3);
        __half* dst = ABh + row * (2*EMB) + c;
        *(__half2*)dst         = __halves2half2(h0,h1);
        *(__half2*)(dst+2)     = __halves2half2(h2,h3);
        *(__half2*)(dst+EMB)   = __halves2half2(l0,l1);
        *(__half2*)(dst+EMB+2) = __halves2half2(l2,l3);
        return;
    }
    id -= 2 * NSPA;
    int tx = tid & 31, ty = tid >> 5;
    bool isW1 = id < NW1;
    int id2 = isW1 ? id : id - NW1;
    int R = isW1 ? EMB : HID;
    const float* W = isW1 ? W1 : W2;
    __half* WT = isW1 ? W1Th : W2Th;
    int rt = R / 32;
    int r0 = (id2 % rt) * 32, c0 = (id2 / rt) * 32;
#pragma unroll
    for (int k = 0; k < 4; ++k)
        tile[k*8+ty][tx] = W[(size_t)(r0 + k*8 + ty) * HID + c0 + tx];
    __syncthreads();
#pragma unroll
    for (int k = 0; k < 4; ++k) {
        int c = c0 + k*8 + ty;
        float v = tile[tx][k*8+ty];
        __half h, l; split_h(v, h, l);
        WT[(size_t)c * (2*R) + r0 + tx]     = h;
        WT[(size_t)c * (2*R) + R + r0 + tx] = l;
    }
}

// ================= softmax stats =================
// Row stats (2048 blocks) + col partials (512 blocks: 16b x 4cc x 8seg)
#define ROWSTAT_BLOCKS (MROWS/8)
#define COLPART_BLOCKS (BSZ*4*8)

__global__ void __launch_bounds__(256)
stats_kernel(const float* __restrict__ E0, const float* __restrict__ E1,
             float* __restrict__ rmax, float* __restrict__ rsum,
             float* __restrict__ cpm, float* __restrict__ cps)
{
    if (blockIdx.x < ROWSTAT_BLOCKS) {
        int r = blockIdx.x * 8 + (threadIdx.x >> 5);
        int lane = threadIdx.x & 31;
        const float* r0p = E0 + (size_t)r * TT;
        const float* r1p = E1 + (size_t)r * TT;
        float v[32], m = -1e30f;
#pragma unroll
        for (int i = 0; i < 8; ++i) {
            float4 a = *(const float4*)(r0p + i*128 + lane*4);
            float4 b = *(const float4*)(r1p + i*128 + lane*4);
            float x0=a.x+b.x, x1=a.y+b.y, x2=a.z+b.z, x3=a.w+b.w;
            v[i*4]=x0; v[i*4+1]=x1; v[i*4+2]=x2; v[i*4+3]=x3;
            m = fmaxf(m, fmaxf(fmaxf(x0,x1), fmaxf(x2,x3)));
        }
#pragma unroll
        for (int o = 16; o > 0; o >>= 1) m = fmaxf(m, __shfl_xor_sync(~0u, m, o));
        float s = 0.f;
#pragma unroll
        for (int i = 0; i < 32; ++i) s += __expf(v[i] - m);
#pragma unroll
        for (int o = 16; o > 0; o >>= 1) s += __shfl_xor_sync(~0u, s, o);
        if (lane == 0) { rmax[r] = m; rsum[r] = s; }
    } else {
        int id = blockIdx.x - ROWSTAT_BLOCKS;       // 0..511
        int b = id >> 5, cc = (id >> 3) & 3, seg = id & 7;
        int c = cc * 256 + threadIdx.x;
        const float* b0 = E0 + (size_t)b * TT * TT + c;
        const float* b1 = E1 + (size_t)b * TT * TT + c;
        float m = -1e30f;
#pragma unroll 4
        for (int a = seg*128; a < seg*128 + 128; ++a)
            m = fmaxf(m, b0[(size_t)a * TT] + b1[(size_t)a * TT]);
        float s = 0.f;
#pragma unroll 4
        for (int a = seg*128; a < seg*128 + 128; ++a)
            s += __expf(b0[(size_t)a * TT] + b1[(size_t)a * TT] - m);
        cpm[(size_t)seg * MROWS + b * TT + c] = m;
        cps[(size_t)seg * MROWS + b * TT + c] = s;
    }
}

__global__ void __launch_bounds__(256)
colcombine_kernel(const float* __restrict__ cpm, const float* __restrict__ cps,
                  float* __restrict__ cmax, float* __restrict__ csum)
{
    int g = blockIdx.x * 256 + threadIdx.x;     // 0..16383
    float m = -1e30f;
#pragma unroll
    for (int s = 0; s < 8; ++s) m = fmaxf(m, cpm[(size_t)s * MROWS + g]);
    float sum = 0.f;
#pragma unroll
    for (int s = 0; s < 8; ++s)
        sum += cps[(size_t)s * MROWS + g] * __expf(cpm[(size_t)s * MROWS + g] - m);
    cmax[g] = m; csum[g] = sum;
}

__global__ void __launch_bounds__(256)
normexp_kernel(const float* __restrict__ E0, const float* __restrict__ E1,
               __half* __restrict__ Pall,
               const float* __restrict__ rmax, const float* __restrict__ rsum,
               const float* __restrict__ cmax, const float* __restrict__ csum)
{
    __shared__ float tile[32][33];
    int b = blockIdx.z, a0 = blockIdx.y * 32, c0 = blockIdx.x * 32;
    int tx = threadIdx.x, ty = threadIdx.y;
    const float* Eb0 = E0 + (size_t)b * TT * TT;
    const float* Eb1 = E1 + (size_t)b * TT * TT;
    __half* P2b = Pall + (size_t)b * TT * TT;
    __half* Pb  = Pall + (size_t)(BSZ + b) * TT * TT;
#pragma unroll
    for (int k = 0; k < 4; ++k) {
        int a = a0 + k*8 + ty;
        size_t off = (size_t)a * TT + c0 + tx;
        float v = Eb0[off] + Eb1[off];
        tile[k*8+ty][tx] = v;
        int grr = b * TT + a;
        Pb[off] = __float2half_rn(__expf(v - rmax[grr]) * __frcp_rn(rsum[grr]));
    }
    __syncthreads();
#pragma unroll
    for (int k = 0; k < 4; ++k) {
        int c = c0 + k*8 + ty;
        float v = tile[tx][k*8+ty];
        int gc = b * TT + c;
        P2b[(size_t)c * TT + a0 + tx] =
            __float2half_rn(__expf(v - cmax[gc]) * __frcp_rn(csum[gc]));
    }
}

// ================= launch =================
extern "C" void kernel_launch(void* const* d_in, const int* in_sizes, int n_in,
                              void* d_out, int out_size)
{
    const float* Ain = (const float*)d_in[0];
    const float* Bin = (const float*)d_in[1];
    const float* W1  = (const float*)d_in[2];
    const float* b1  = (const float*)d_in[3];
    const float* W2  = (const float*)d_in[4];
    const float* b2  = (const float*)d_in[5];
    float* outp = (float*)d_out;

    __half *ABh, *W1Th, *W2Th, *Hh, *Fh, *Pall;
    float *E, *rm, *rs, *cm, *cs, *cpm, *cps;
    cudaGetSymbolAddress((void**)&ABh,  g_ABh);
    cudaGetSymbolAddress((void**)&W1Th, g_W1Th);
    cudaGetSymbolAddress((void**)&W2Th, g_W2Th);
    cudaGetSymbolAddress((void**)&Hh,   g_Hh);
    cudaGetSymbolAddress((void**)&Fh,   g_Fh);
    cudaGetSymbolAddress((void**)&E,    g_E);
    cudaGetSymbolAddress((void**)&Pall, g_Pall);
    cudaGetSymbolAddress((void**)&rm,   g_rmax);
    cudaGetSymbolAddress((void**)&rs,   g_rsum);
    cudaGetSymbolAddress((void**)&cm,   g_cmax);
    cudaGetSymbolAddress((void**)&cs,   g_csum);
    cudaGetSymbolAddress((void**)&cpm,  g_cpm);
    cudaGetSymbolAddress((void**)&cps,  g_cps);

    float* E1 = E + (size_t)BSZ * TT * TT;

    cudaFuncSetAttribute(gemm_h<true,  true,  true,  false, false>, cudaFuncAttributeMaxDynamicSharedMemorySize, SMEM3);
    cudaFuncSetAttribute(gemm_h<true,  false, false, false, true >, cudaFuncAttributeMaxDynamicSharedMemorySize, SMEM3);
    cudaFuncSetAttribute(gemm_h<false, false, false, true,  false>, cudaFuncAttributeMaxDynamicSharedMemorySize, SMEMP);

    // 1) prep
    prep_kernel<<<PREP_BLOCKS, 256>>>(Ain, Bin, W1, W2, ABh, W1Th, W2Th);

    // 2) MLP layer 1
    gemm_h<true, true, true, false, false><<<dim3(HID/BN, 2*MROWS/BM, 1), NTHR, SMEM3>>>(
        ABh, 2*EMB, 0, W1Th, 2*EMB, 0, b1, Hh, 2*HID, 0, HID, EMB, EMB);

    // 3) MLP layer 2
    gemm_h<true, true, true, false, false><<<dim3(HID/BN, 2*MROWS/BM, 1), NTHR, SMEM3>>>(
        Hh, 2*HID, 0, W2Th, 2*HID, 0, b2, Fh, 2*HID, 0, HID, HID, HID);

    // 4) e = f_A @ f_B^T, K split in two halves (z = 32; out E / E1)
    gemm_h<true, false, false, false, true><<<dim3(TT/BN, TT/BM, 2*BSZ), NTHR, SMEM3>>>(
        Fh, 2*HID, (unsigned long long)TT*2*HID,
        Fh + (size_t)MROWS*2*HID, 2*HID, (unsigned long long)TT*2*HID,
        nullptr, E, TT, (unsigned long long)TT*TT, TT, HID/2, HID);

    // 5) stats: row (2048) + col partials (512)
    stats_kernel<<<ROWSTAT_BLOCKS + COLPART_BLOCKS, 256>>>(E, E1, rm, rs, cpm, cps);
    colcombine_kernel<<<MROWS/256, 256>>>(cpm, cps, cm, cs);

    // 6) normalize -> Pall = [P2 | P]
    normexp_kernel<<<dim3(TT/32, TT/32, BSZ), dim3(32, 8)>>>(E, E1, Pall, rm, rs, cm, cs);

    // 7) alpha (z 0..15: P2 @ A) + beta (z 16..31: P @ B) in one launch
    gemm_h<false, false, false, true, false><<<dim3(EMB/BN, TT/BM, 2*BSZ), NTHR, SMEMP>>>(
        Pall, TT, (unsigned long long)TT*TT,
        ABh, 2*EMB, (unsigned long long)TT*2*EMB,
        nullptr, outp, EMB, (unsigned long long)TT*EMB, EMB, TT, 0);
}

// round 14
// speedup vs baseline: 1.3231x; 1.0440x over previous
#include <cuda_runtime.h>
#include <cuda_fp16.h>
#include <cstdint>

#define BSZ 16
#define TT  1024
#define EMB 768
#define HID 1024
#define MROWS (BSZ*TT)

// ================= scratch =================
__device__ __align__(128) __half g_ABh [(size_t)2*MROWS*2*EMB];
__device__ __align__(128) __half g_W1Th[(size_t)HID*2*EMB];
__device__ __align__(128) __half g_W2Th[(size_t)HID*2*HID];
__device__ __align__(128) __half g_Hh  [(size_t)2*MROWS*2*HID];
__device__ __align__(128) __half g_Fh  [(size_t)2*MROWS*2*HID];
__device__ __align__(128) float  g_E   [(size_t)BSZ*TT*TT];
__device__ __align__(128) __half g_Pall[(size_t)2*BSZ*TT*TT];   // [P2 | P]
__device__ float g_rmax[MROWS], g_rsum[MROWS], g_cmax[MROWS], g_csum[MROWS];
__device__ float g_rpm[8*MROWS], g_rps[8*MROWS];   // row partials (per n-block)
__device__ float g_cpm[8*MROWS], g_cps[8*MROWS];   // col partials (per m-block)

// ================= helpers =================
__device__ __forceinline__ uint32_t smem_u32(const void* p) {
    uint32_t a;
    asm("{ .reg .u64 t; cvta.to.shared.u64 t, %1; cvt.u32.u64 %0, t; }" : "=r"(a) : "l"(p));
    return a;
}
__device__ __forceinline__ void mma_f16(float* d, const uint32_t* a, const uint32_t* b) {
    asm volatile("mma.sync.aligned.m16n8k16.row.col.f32.f16.f16.f32 "
        "{%0,%1,%2,%3}, {%4,%5,%6,%7}, {%8,%9}, {%0,%1,%2,%3};"
        : "+f"(d[0]), "+f"(d[1]), "+f"(d[2]), "+f"(d[3])
        : "r"(a[0]), "r"(a[1]), "r"(a[2]), "r"(a[3]), "r"(b[0]), "r"(b[1]));
}
__device__ __forceinline__ void ldsm(uint32_t* r, uint32_t a) {
    asm volatile("ldmatrix.sync.aligned.m8n8.x4.shared.b16 {%0,%1,%2,%3}, [%4];"
        : "=r"(r[0]), "=r"(r[1]), "=r"(r[2]), "=r"(r[3]) : "r"(a));
}
__device__ __forceinline__ void ldsmT(uint32_t* r, uint32_t a) {
    asm volatile("ldmatrix.sync.aligned.m8n8.x4.trans.shared.b16 {%0,%1,%2,%3}, [%4];"
        : "=r"(r[0]), "=r"(r[1]), "=r"(r[2]), "=r"(r[3]) : "r"(a));
}
__device__ __forceinline__ void cp16(uint32_t d, const void* s) {
    asm volatile("cp.async.cg.shared.global [%0], [%1], 16;" :: "r"(d), "l"(s) : "memory");
}
__device__ __forceinline__ void split_h(float v, __half& hi, __half& lo) {
    hi = __float2half_rn(v);
    lo = __float2half_rn(v - __half2float(hi));
}
// online softmax merge: (m,s) <- merge((m,s),(om,os))
__device__ __forceinline__ void sm_merge(float& m, float& s, float om, float os) {
    float M = fmaxf(m, om);
    s = s * __expf(m - M) + os * __expf(om - M);
    m = M;
}

// ================= fp16 mma GEMM (fused 3-term split) =================
#define BM 128
#define BN 128
#define BKH 32
#define NTHR 256
#define SROW 80
#define SROWT 272
#define STG3 40960u
#define STGP 18944u
#define ALO_OFF 10240u
#define BHI_OFF 20480u
#define BLO_OFF 30720u
#define BT_OFF  10240u
#define SMEM3 (2*40960)
#define SMEMP (2*18944)

template<bool SPLIT3>
__device__ __forceinline__ void cp_stage32(uint32_t st,
    const __half* __restrict__ ga, int lda,
    const __half* __restrict__ gb, int ldb, int loK, int tid)
{
    if (SPLIT3) {
#pragma unroll
        for (int i = 0; i < 8; ++i) {
            int u = tid + i * NTHR;
            int mat = u >> 9;
            int r = (u >> 2) & 127;
            int c = u & 3;
            const __half* src = ((mat < 2) ? ga : gb)
                              + ((mat & 1) ? loK : 0)
                              + (size_t)r * ((mat < 2) ? lda : ldb) + c * 8;
            cp16(st + (uint32_t)((mat * 128 + r) * SROW + c * 16), src);
        }
    } else {
#pragma unroll
        for (int i = 0; i < 2; ++i) {
            int u = tid + i * NTHR, r = u >> 2, c = u & 3;
            cp16(st + (uint32_t)(r * SROW + c * 16), ga + (size_t)r * lda + c * 8);
        }
#pragma unroll
        for (int i = 0; i < 2; ++i) {
            int u = tid + i * NTHR, r = u >> 4, c = u & 15;
            cp16(st + BT_OFF + (uint32_t)(r * SROWT + c * 16), gb + (size_t)r * ldb + c * 8);
        }
    }
}

template<bool SPLIT3, bool BIASRELU, bool HALFSPLITOUT, bool SWAPOUT, bool STATS>
__global__ void __launch_bounds__(NTHR, 2)
gemm_h(const __half* __restrict__ Aop, int lda, unsigned long long sA,
       const __half* __restrict__ Bop, int ldb, unsigned long long sB,
       const float* __restrict__ bias,
       void* __restrict__ Cv, int ldc, unsigned long long sC,
       int N, int K, int loK,
       float* __restrict__ rpm, float* __restrict__ rps,
       float* __restrict__ cpm, float* __restrict__ cps)
{
    extern __shared__ __align__(128) __half smh[];
    uint32_t sbase = smem_u32(smh);
    constexpr uint32_t STG = SPLIT3 ? STG3 : STGP;
    const int tid = threadIdx.x, lane = tid & 31, wid = tid >> 5;
    const int wm = wid >> 2, wn = wid & 3, gr = lane >> 2, tc = lane & 3;
    const int m0 = blockIdx.y * BM, n0 = blockIdx.x * BN;
    const int z  = blockIdx.z;

    const __half* Abase = Aop + (size_t)z * sA + (size_t)m0 * lda;
    const __half* Bbase = SPLIT3
        ? (Bop + (size_t)z * sB + (size_t)n0 * ldb)
        : (Bop + (size_t)z * sB + n0);
    const int NT = K / BKH;

    const int lg = lane >> 3, r8 = lane & 7;
    uint32_t aOff[4], bOff[2];
#pragma unroll
    for (int mi = 0; mi < 4; ++mi)
        aOff[mi] = (uint32_t)((wm * 64 + mi * 16 + (lg & 1) * 8 + r8) * SROW
                              + (lg >> 1) * 16);
#pragma unroll
    for (int pn = 0; pn < 2; ++pn) {
        if (SPLIT3)
            bOff[pn] = (uint32_t)((wn * 32 + pn * 16 + (lg >> 1) * 8 + r8) * SROW
                                  + (lg & 1) * 16);
        else
            bOff[pn] = (uint32_t)(((lg & 1) * 8 + r8) * SROWT
                                  + (wn * 32 + pn * 16 + (lg >> 1) * 8) * 2);
    }

    float acc[4][4][4];
#pragma unroll
    for (int i = 0; i < 4; ++i)
#pragma unroll
        for (int j = 0; j < 4; ++j)
#pragma unroll
            for (int k = 0; k < 4; ++k) acc[i][j][k] = 0.f;

    cp_stage32<SPLIT3>(sbase, Abase, lda, Bbase, ldb, loK, tid);
    asm volatile("cp.async.commit_group;" ::: "memory");

#pragma unroll 1
    for (int kt = 0; kt < NT; ++kt) {
        asm volatile("cp.async.wait_group 0;" ::: "memory");
        __syncthreads();
        if (kt + 1 < NT) {
            uint32_t st = sbase + (uint32_t)((kt + 1) & 1) * STG;
            const __half* ga = Abase + (kt + 1) * BKH;
            const __half* gb = SPLIT3 ? (Bbase + (kt + 1) * BKH)
                                      : (Bbase + (size_t)(kt + 1) * BKH * ldb);
            cp_stage32<SPLIT3>(st, ga, lda, gb, ldb, loK, tid);
            asm volatile("cp.async.commit_group;" ::: "memory");
        }
        uint32_t st = sbase + (uint32_t)(kt & 1) * STG;
#pragma unroll
        for (int ks = 0; ks < 2; ++ks) {
            if (SPLIT3) {
                const uint32_t kb = (uint32_t)(ks * 32);
                uint32_t bh[4][2], bl[4][2];
#pragma unroll
                for (int pn = 0; pn < 2; ++pn) {
                    uint32_t t[4];
                    ldsm(t, st + BHI_OFF + bOff[pn] + kb);
                    bh[2*pn][0]=t[0]; bh[2*pn][1]=t[1]; bh[2*pn+1][0]=t[2]; bh[2*pn+1][1]=t[3];
                    ldsm(t, st + BLO_OFF + bOff[pn] + kb);
                    bl[2*pn][0]=t[0]; bl[2*pn][1]=t[1]; bl[2*pn+1][0]=t[2]; bl[2*pn+1][1]=t[3];
                }
#pragma unroll
                for (int mi = 0; mi < 4; ++mi) {
                    uint32_t ah[4], al[4];
                    ldsm(ah, st + aOff[mi] + kb);
                    ldsm(al, st + ALO_OFF + aOff[mi] + kb);
#pragma unroll
                    for (int ni = 0; ni < 4; ++ni) mma_f16(acc[mi][ni], ah, bh[ni]);
#pragma unroll
                    for (int ni = 0; ni < 4; ++ni) mma_f16(acc[mi][ni], al, bh[ni]);
#pragma unroll
                    for (int ni = 0; ni < 4; ++ni) mma_f16(acc[mi][ni], ah, bl[ni]);
                }
            } else {
                const uint32_t kbA = (uint32_t)(ks * 32);
                const uint32_t kbB = (uint32_t)(ks * 16 * SROWT);
                uint32_t bf[4][2];
#pragma unroll
                for (int pn = 0; pn < 2; ++pn) {
                    uint32_t t[4];
                    ldsmT(t, st + BT_OFF + bOff[pn] + kbB);
                    bf[2*pn][0]=t[0]; bf[2*pn][1]=t[1]; bf[2*pn+1][0]=t[2]; bf[2*pn+1][1]=t[3];
                }
#pragma unroll
                for (int mi = 0; mi < 4; ++mi) {
                    uint32_t af[4];
                    ldsm(af, st + aOff[mi] + kbA);
#pragma unroll
                    for (int ni = 0; ni < 4; ++ni) mma_f16(acc[mi][ni], af, bf[ni]);
                }
            }
        }
    }

    // ---- store ----
    int ob = SWAPOUT ? ((z < BSZ) ? (BSZ + z) : (z - BSZ)) : z;
#pragma unroll
    for (int ni = 0; ni < 4; ++ni) {
        int col = n0 + wn * 32 + ni * 8 + 2 * tc;
        float b0 = 0.f, b1 = 0.f;
        if (BIASRELU) { b0 = __ldg(bias + col); b1 = __ldg(bias + col + 1); }
#pragma unroll
        for (int mi = 0; mi < 4; ++mi) {
            int row0 = m0 + wm * 64 + mi * 16 + gr;
            float v00 = acc[mi][ni][0], v01 = acc[mi][ni][1];
            float v10 = acc[mi][ni][2], v11 = acc[mi][ni][3];
            if (BIASRELU) {
                v00 = fmaxf(v00 + b0, 0.f); v01 = fmaxf(v01 + b1, 0.f);
                v10 = fmaxf(v10 + b0, 0.f); v11 = fmaxf(v11 + b1, 0.f);
                acc[mi][ni][0]=v00; acc[mi][ni][1]=v01; acc[mi][ni][2]=v10; acc[mi][ni][3]=v11;
            }
            if (HALFSPLITOUT) {
                __half* C = (__half*)Cv + (size_t)ob * sC;
                __half h00,l00,h01,l01,h10,l10,h11,l11;
                split_h(v00,h00,l00); split_h(v01,h01,l01);
                split_h(v10,h10,l10); split_h(v11,h11,l11);
                __half* p0 = C + (size_t)row0 * ldc + col;
                __half* p1 = C + (size_t)(row0 + 8) * ldc + col;
                *(__half2*)p0       = __halves2half2(h00, h01);
                *(__half2*)(p0 + N) = __halves2half2(l00, l01);
                *(__half2*)p1       = __halves2half2(h10, h11);
                *(__half2*)(p1 + N) = __halves2half2(l10, l11);
            } else {
                float* C = (float*)Cv + (size_t)ob * sC;
                *(float2*)(C + (size_t)row0 * ldc + col)       = make_float2(v00, v01);
                *(float2*)(C + (size_t)(row0 + 8) * ldc + col) = make_float2(v10, v11);
            }
        }
    }

    // ---- fused softmax partial stats (e-GEMM only) ----
    if (STATS) {
        __syncthreads();                       // stage smem free now
        float2* smR = (float2*)smh;            // [128][4]  (row, wn)
        float2* smC = ((float2*)smh) + 512;    // [128][2]  (col, wm)
        // row partials: thread covers 8 rows x 8 cols
#pragma unroll
        for (int mi = 0; mi < 4; ++mi)
#pragma unroll
            for (int h = 0; h < 2; ++h) {
                float m = -1e30f;
#pragma unroll
                for (int ni = 0; ni < 4; ++ni)
                    m = fmaxf(m, fmaxf(acc[mi][ni][2*h], acc[mi][ni][2*h+1]));
                float s = 0.f;
#pragma unroll
                for (int ni = 0; ni < 4; ++ni)
                    s += __expf(acc[mi][ni][2*h] - m) + __expf(acc[mi][ni][2*h+1] - m);
#pragma unroll
                for (int o = 1; o <= 2; o <<= 1)
                    sm_merge(m, s, __shfl_xor_sync(~0u, m, o), __shfl_xor_sync(~0u, s, o));
                if (tc == 0)
                    smR[(wm*64 + mi*16 + h*8 + gr) * 4 + wn] = make_float2(m, s);
            }
        // col partials: thread covers 8 cols x 8 rows
#pragma unroll
        for (int ni = 0; ni < 4; ++ni)
#pragma unroll
            for (int j = 0; j < 2; ++j) {
                float m = -1e30f;
#pragma unroll
                for (int mi = 0; mi < 4; ++mi)
                    m = fmaxf(m, fmaxf(acc[mi][ni][j], acc[mi][ni][j+2]));
                float s = 0.f;
#pragma unroll
                for (int mi = 0; mi < 4; ++mi)
                    s += __expf(acc[mi][ni][j] - m) + __expf(acc[mi][ni][j+2] - m);
#pragma unroll
                for (int o = 4; o <= 16; o <<= 1)
                    sm_merge(m, s, __shfl_xor_sync(~0u, m, o), __shfl_xor_sync(~0u, s, o));
                if (gr == 0)
                    smC[(wn*32 + ni*8 + 2*tc + j) * 2 + wm] = make_float2(m, s);
            }
        __syncthreads();
        if (tid < 128) {
            float2 p = smR[tid * 4];
            float m = p.x, s = p.y;
#pragma unroll
            for (int w = 1; w < 4; ++w) {
                float2 q = smR[tid * 4 + w];
                sm_merge(m, s, q.x, q.y);
            }
            size_t idx = (size_t)blockIdx.x * MROWS + (size_t)z * TT + m0 + tid;
            rpm[idx] = m; rps[idx] = s;
        } else {
            int cl = tid - 128;
            float2 p = smC[cl * 2];
            float m = p.x, s = p.y;
            float2 q = smC[cl * 2 + 1];
            sm_merge(m, s, q.x, q.y);
            size_t idx = (size_t)blockIdx.y * MROWS + (size_t)z * TT + n0 + cl;
            cpm[idx] = m; cps[idx] = s;
        }
    }
}

// ================= prep =================
#define NSPA ((MROWS*EMB)/1024)
#define NW1  ((EMB/32)*(HID/32))
#define NW2  ((HID/32)*(HID/32))
#define PREP_BLOCKS (2*NSPA + NW1 + NW2)

__global__ void __launch_bounds__(256)
prep_kernel(const float* __restrict__ A, const float* __restrict__ Bn,
            const float* __restrict__ W1, const float* __restrict__ W2,
            __half* __restrict__ ABh, __half* __restrict__ W1Th,
            __half* __restrict__ W2Th)
{
    __shared__ float tile[32][33];
    int id = blockIdx.x, tid = threadIdx.x;
    if (id < 2 * NSPA) {
        bool isA = id < NSPA;
        const float4* src = (const float4*)(isA ? A : Bn);
        size_t i = (size_t)(id - (isA ? 0 : NSPA)) * 256 + tid;
        float4 v = src[i];
        size_t row = i / (EMB/4) + (isA ? 0 : (size_t)MROWS);
        size_t c = (i % (EMB/4)) * 4;
        __half h0,l0,h1,l1,h2,l2,h3,l3;
        split_h(v.x,h0,l0); split_h(v.y,h1,l1); split_h(v.z,h2,l2); split_h(v.w,h3,l3);
        __half* dst = ABh + row * (2*EMB) + c;
        *(__half2*)dst         = __halves2half2(h0,h1);
        *(__half2*)(dst+2)     = __halves2half2(h2,h3);
        *(__half2*)(dst+EMB)   = __halves2half2(l0,l1);
        *(__half2*)(dst+EMB+2) = __halves2half2(l2,l3);
        return;
    }
    id -= 2 * NSPA;
    int tx = tid & 31, ty = tid >> 5;
    bool isW1 = id < NW1;
    int id2 = isW1 ? id : id - NW1;
    int R = isW1 ? EMB : HID;
    const float* W = isW1 ? W1 : W2;
    __half* WT = isW1 ? W1Th : W2Th;
    int rt = R / 32;
    int r0 = (id2 % rt) * 32, c0 = (id2 / rt) * 32;
#pragma unroll
    for (int k = 0; k < 4; ++k)
        tile[k*8+ty][tx] = W[(size_t)(r0 + k*8 + ty) * HID + c0 + tx];
    __syncthreads();
#pragma unroll
    for (int k = 0; k < 4; ++k) {
        int c = c0 + k*8 + ty;
        float v = tile[tx][k*8+ty];
        __half h, l; split_h(v, h, l);
        WT[(size_t)c * (2*R) + r0 + tx]     = h;
        WT[(size_t)c * (2*R) + R + r0 + tx] = l;
    }
}

// ================= combine partials =================
__global__ void __launch_bounds__(256)
combine_kernel(const float* __restrict__ rpm, const float* __restrict__ rps,
               const float* __restrict__ cpm, const float* __restrict__ cps,
               float* __restrict__ rmax, float* __restrict__ rsum,
               float* __restrict__ cmax, float* __restrict__ csum)
{
    int g = blockIdx.x * 256 + threadIdx.x;       // 0..2*MROWS-1
    const float *pm, *ps;
    float *om, *os;
    int id = g;
    if (g < MROWS) { pm = rpm; ps = rps; om = rmax; os = rsum; }
    else { id = g - MROWS; pm = cpm; ps = cps; om = cmax; os = csum; }
    float m = pm[id], s = ps[id];
#pragma unroll
    for (int k = 1; k < 8; ++k)
        sm_merge(m, s, pm[(size_t)k * MROWS + id], ps[(size_t)k * MROWS + id]);
    om[id] = m; os[id] = s;
}

// ================= normalize =================
__global__ void __launch_bounds__(256)
normexp_kernel(const float* __restrict__ E, __half* __restrict__ Pall,
               const float* __restrict__ rmax, const float* __restrict__ rsum,
               const float* __restrict__ cmax, const float* __restrict__ csum)
{
    __shared__ float tile[32][33];
    int b = blockIdx.z, a0 = blockIdx.y * 32, c0 = blockIdx.x * 32;
    int tx = threadIdx.x, ty = threadIdx.y;
    const float* Eb = E + (size_t)b * TT * TT;
    __half* P2b = Pall + (size_t)b * TT * TT;
    __half* Pb  = Pall + (size_t)(BSZ + b) * TT * TT;
#pragma unroll
    for (int k = 0; k < 4; ++k) {
        int a = a0 + k*8 + ty;
        float v = Eb[(size_t)a * TT + c0 + tx];
        tile[k*8+ty][tx] = v;
        int grr = b * TT + a;
        Pb[(size_t)a * TT + c0 + tx] =
            __float2half_rn(__expf(v - rmax[grr]) * __frcp_rn(rsum[grr]));
    }
    __syncthreads();
#pragma unroll
    for (int k = 0; k < 4; ++k) {
        int c = c0 + k*8 + ty;
        float v = tile[tx][k*8+ty];
        int gc = b * TT + c;
        P2b[(size_t)c * TT + a0 + tx] =
            __float2half_rn(__expf(v - cmax[gc]) * __frcp_rn(csum[gc]));
    }
}

// ================= launch =================
extern "C" void kernel_launch(void* const* d_in, const int* in_sizes, int n_in,
                              void* d_out, int out_size)
{
    const float* Ain = (const float*)d_in[0];
    const float* Bin = (const float*)d_in[1];
    const float* W1  = (const float*)d_in[2];
    const float* b1  = (const float*)d_in[3];
    const float* W2  = (const float*)d_in[4];
    const float* b2  = (const float*)d_in[5];
    float* outp = (float*)d_out;

    __half *ABh, *W1Th, *W2Th, *Hh, *Fh, *Pall;
    float *E, *rm, *rs, *cm, *cs, *rpm, *rps, *cpm, *cps;
    cudaGetSymbolAddress((void**)&ABh,  g_ABh);
    cudaGetSymbolAddress((void**)&W1Th, g_W1Th);
    cudaGetSymbolAddress((void**)&W2Th, g_W2Th);
    cudaGetSymbolAddress((void**)&Hh,   g_Hh);
    cudaGetSymbolAddress((void**)&Fh,   g_Fh);
    cudaGetSymbolAddress((void**)&E,    g_E);
    cudaGetSymbolAddress((void**)&Pall, g_Pall);
    cudaGetSymbolAddress((void**)&rm,   g_rmax);
    cudaGetSymbolAddress((void**)&rs,   g_rsum);
    cudaGetSymbolAddress((void**)&cm,   g_cmax);
    cudaGetSymbolAddress((void**)&cs,   g_csum);
    cudaGetSymbolAddress((void**)&rpm,  g_rpm);
    cudaGetSymbolAddress((void**)&rps,  g_rps);
    cudaGetSymbolAddress((void**)&cpm,  g_cpm);
    cudaGetSymbolAddress((void**)&cps,  g_cps);

    cudaFuncSetAttribute(gemm_h<true,  true,  true,  false, false>, cudaFuncAttributeMaxDynamicSharedMemorySize, SMEM3);
    cudaFuncSetAttribute(gemm_h<true,  false, false, false, true >, cudaFuncAttributeMaxDynamicSharedMemorySize, SMEM3);
    cudaFuncSetAttribute(gemm_h<false, false, false, true,  false>, cudaFuncAttributeMaxDynamicSharedMemorySize, SMEMP);

    // 1) prep
    prep_kernel<<<PREP_BLOCKS, 256>>>(Ain, Bin, W1, W2, ABh, W1Th, W2Th);

    // 2) MLP layer 1
    gemm_h<true, true, true, false, false><<<dim3(HID/BN, 2*MROWS/BM, 1), NTHR, SMEM3>>>(
        ABh, 2*EMB, 0, W1Th, 2*EMB, 0, b1, Hh, 2*HID, 0, HID, EMB, EMB,
        nullptr, nullptr, nullptr, nullptr);

    // 3) MLP layer 2
    gemm_h<true, true, true, false, false><<<dim3(HID/BN, 2*MROWS/BM, 1), NTHR, SMEM3>>>(
        Hh, 2*HID, 0, W2Th, 2*HID, 0, b2, Fh, 2*HID, 0, HID, HID, HID,
        nullptr, nullptr, nullptr, nullptr);

    // 4) e = f_A @ f_B^T with fused softmax partial stats
    gemm_h<true, false, false, false, true><<<dim3(TT/BN, TT/BM, BSZ), NTHR, SMEM3>>>(
        Fh, 2*HID, (unsigned long long)TT*2*HID,
        Fh + (size_t)MROWS*2*HID, 2*HID, (unsigned long long)TT*2*HID,
        nullptr, E, TT, (unsigned long long)TT*TT, TT, HID, HID,
        rpm, rps, cpm, cps);

    // 5) combine partials -> row/col (max, sum)
    combine_kernel<<<2*MROWS/256, 256>>>(rpm, rps, cpm, cps, rm, rs, cm, cs);

    // 6) normalize -> Pall = [P2 | P]
    normexp_kernel<<<dim3(TT/32, TT/32, BSZ), dim3(32, 8)>>>(E, Pall, rm, rs, cm, cs);

    // 7) alpha (z 0..15: P2 @ A) + beta (z 16..31: P @ B) in one launch
    gemm_h<false, false, false, true, false><<<dim3(EMB/BN, TT/BM, 2*BSZ), NTHR, SMEMP>>>(
        Pall, TT, (unsigned long long)TT*TT,
        ABh, 2*EMB, (unsigned long long)TT*2*EMB,
        nullptr, outp, EMB, (unsigned long long)TT*EMB, EMB, TT, 0,
        nullptr, nullptr, nullptr, nullptr);
}